// round 1
// baseline (speedup 1.0000x reference)
#include <cuda_runtime.h>
#include <math.h>
#include <stdint.h>

// Problem dims
#define B_    512
#define NSLOT 128
#define IN_   2048
#define MEMD  64
#define OUT_  2048
#define NC    130      // fused front-GEMM cols: 64 (q) + 1 (forget_x) + 65 (remember_x)
#define CONC  2176     // IN + 2*MEM

// ---------------- scratch (static __device__, no allocations) ----------------
__device__ float g_Wcat[IN_ * NC];      // packed [2048,130] weight for front GEMM
__device__ float g_T[B_ * NC];          // front GEMM result (bias-initialized, atomically accumulated)
__device__ float g_interm[B_ * CONC];   // [x | active_recall | passive_recall]

// ---------------- f32x2 packed-FMA helpers (full-rate fp32 on sm_103a) -------
typedef unsigned long long u64t;
__device__ __forceinline__ u64t pk2(float lo, float hi) {
    u64t r; asm("mov.b64 %0, {%1,%2};" : "=l"(r) : "f"(lo), "f"(hi)); return r;
}
__device__ __forceinline__ void fma2(u64t& d, u64t a, u64t b) {
    asm("fma.rn.f32x2 %0, %1, %2, %3;" : "=l"(d) : "l"(a), "l"(b), "l"(d));
}
__device__ __forceinline__ float2 upk2(u64t v) {
    float lo, hi; asm("mov.b64 {%0,%1}, %2;" : "=f"(lo), "=f"(hi) : "l"(v));
    return make_float2(lo, hi);
}

// ============================================================================
// Kernel 0: pack Wcat = [W_ar | W_f_top | W_r_top], init T with biases
// ============================================================================
__global__ void pack_init_kernel(const float* __restrict__ W_ar, const float* __restrict__ b_ar,
                                 const float* __restrict__ W_f,  const float* __restrict__ b_f,
                                 const float* __restrict__ W_r,  const float* __restrict__ b_r)
{
    int i = blockIdx.x * blockDim.x + threadIdx.x;
    const int NW = IN_ * NC;
    if (i < NW) {
        int k = i / NC, j = i - k * NC;
        float v;
        if (j < 64)       v = W_ar[k * 64 + j];
        else if (j == 64) v = W_f[k];
        else              v = W_r[k * 65 + (j - 65)];
        g_Wcat[i] = v;
    } else if (i < NW + B_ * NC) {
        int r = i - NW;
        int j = r % NC;
        float v;
        if (j < 64)       v = b_ar[j];
        else if (j == 64) v = b_f[0];
        else              v = b_r[j - 65];
        g_T[r] = v;
    }
}

// ============================================================================
// Kernel 1: front GEMM  T += x[512,2048] @ Wcat[2048,130]   (split-K, atomic)
// grid (8, 3, 8), 256 threads, BM=BN=64, BK=16, 16 ktiles per z-slice
// ============================================================================
__global__ __launch_bounds__(256) void gemm1_kernel(const float* __restrict__ x)
{
    __shared__ float As[16][68];
    __shared__ float Bs[16][68];
    int t  = threadIdx.x;
    int tx = t & 15, ty = t >> 4;
    int bm0 = blockIdx.x * 64;
    int bn0 = blockIdx.y * 64;
    int k0b = blockIdx.z * 256;

    float acc[4][4] = {};

    for (int kt = 0; kt < 16; kt++) {
        int k0 = k0b + kt * 16;
        // A tile 64x16: each thread one float4 (row = t>>2, kq = t&3)
        {
            int row = t >> 2, kq = t & 3;
            float4 v = *(const float4*)&x[(size_t)(bm0 + row) * IN_ + k0 + kq * 4];
            As[kq * 4 + 0][row] = v.x;
            As[kq * 4 + 1][row] = v.y;
            As[kq * 4 + 2][row] = v.z;
            As[kq * 4 + 3][row] = v.w;
        }
        // B tile 16x64 (bounds on NC=130)
        {
            int kr = t >> 4, cq = t & 15;
            #pragma unroll
            for (int j = 0; j < 4; j++) {
                int col = bn0 + cq * 4 + j;
                Bs[kr][cq * 4 + j] = (col < NC) ? g_Wcat[(size_t)(k0 + kr) * NC + col] : 0.f;
            }
        }
        __syncthreads();
        #pragma unroll
        for (int k = 0; k < 16; k++) {
            float a0 = As[k][ty * 4 + 0], a1 = As[k][ty * 4 + 1];
            float a2 = As[k][ty * 4 + 2], a3 = As[k][ty * 4 + 3];
            float b0 = Bs[k][tx * 4 + 0], b1 = Bs[k][tx * 4 + 1];
            float b2 = Bs[k][tx * 4 + 2], b3 = Bs[k][tx * 4 + 3];
            acc[0][0] += a0 * b0; acc[0][1] += a0 * b1; acc[0][2] += a0 * b2; acc[0][3] += a0 * b3;
            acc[1][0] += a1 * b0; acc[1][1] += a1 * b1; acc[1][2] += a1 * b2; acc[1][3] += a1 * b3;
            acc[2][0] += a2 * b0; acc[2][1] += a2 * b1; acc[2][2] += a2 * b2; acc[2][3] += a2 * b3;
            acc[3][0] += a3 * b0; acc[3][1] += a3 * b1; acc[3][2] += a3 * b2; acc[3][3] += a3 * b3;
        }
        __syncthreads();
    }
    #pragma unroll
    for (int i = 0; i < 4; i++) {
        int row = bm0 + ty * 4 + i;
        #pragma unroll
        for (int j = 0; j < 4; j++) {
            int col = bn0 + tx * 4 + j;
            if (col < NC) atomicAdd(&g_T[(size_t)row * NC + col], acc[i][j]);
        }
    }
}

// ============================================================================
// Kernel 2: per-batch fused attention + softmax + recalls + memory update
// grid 512, 256 threads, dynamic smem ~53 KB
// ============================================================================
#define FUSED_SMEM_FLOATS (8320 + 4160 + 64*3 + 65 + 128*4 + 8)
#define FUSED_SMEM_BYTES  (FUSED_SMEM_FLOATS * 4)

__global__ __launch_bounds__(256) void fused_mem_kernel(
    const float* __restrict__ x, const float* __restrict__ memory,
    const float* __restrict__ W_pr, const float* __restrict__ b_pr,
    const float* __restrict__ W_f,  const float* __restrict__ W_r,
    float* __restrict__ new_mem)
{
    extern __shared__ float sm[];
    float* mem_s = sm;                    // [128][65]  (padded rows)
    float* wrb_s = sm + 8320;             // [64][65]   W_r bottom block
    float* q_s   = wrb_s + 4160;          // 64
    float* wpr_s = q_s + 64;              // 64
    float* wfb_s = wpr_s + 64;            // 64  W_f bottom
    float* rx_s  = wfb_s + 64;            // 65  remember_x (+bias)
    float* sc_s  = rx_s + 65;             // 128 active scores
    float* ps_s  = sc_s + 128;            // 128 passive scores
    float* f_s   = ps_s + 128;            // 128 forget gates
    float* g_s   = f_s + 128;             // 128 remember gates (last col)
    float* red   = g_s + 128;             // 8 scratch

    int b = blockIdx.x, t = threadIdx.x;
    const float* mg = memory + (size_t)b * (NSLOT * MEMD);

    for (int i = t; i < NSLOT * MEMD; i += 256)
        mem_s[(i >> 6) * 65 + (i & 63)] = mg[i];
    for (int i = t; i < 64 * 65; i += 256)
        wrb_s[i] = W_r[IN_ * 65 + i];
    if (t < 64) {
        q_s[t]   = g_T[(size_t)b * NC + t];
        wpr_s[t] = W_pr[t];
        wfb_s[t] = W_f[IN_ + t];
    }
    if (t < 65) rx_s[t] = g_T[(size_t)b * NC + 65 + t];
    if (t == 0) { red[6] = g_T[(size_t)b * NC + 64]; red[7] = b_pr[0]; }
    __syncthreads();

    // per-slot scores + gates
    if (t < NSLOT) {
        const float* mr = mem_s + t * 65;
        float s = 0.f, p = 0.f, f = 0.f, g = 0.f;
        #pragma unroll 8
        for (int k = 0; k < 64; k++) {
            float mv = mr[k];
            s += mv * q_s[k];
            p += mv * wpr_s[k];
            f += mv * wfb_s[k];
            g += mv * wrb_s[k * 65 + 64];
        }
        sc_s[t] = s;
        ps_s[t] = p + red[7];
        f_s[t]  = 1.1f / (1.f + expf(-(f + red[6])));
        g_s[t]  = g + rx_s[64];
    }
    __syncthreads();

    // softmax over 128 slots (stable), for both score sets
    if (t < 32) {
        float m1 = -1e30f, m2 = -1e30f;
        for (int i = t; i < 128; i += 32) { m1 = fmaxf(m1, sc_s[i]); m2 = fmaxf(m2, ps_s[i]); }
        #pragma unroll
        for (int o = 16; o; o >>= 1) {
            m1 = fmaxf(m1, __shfl_xor_sync(0xffffffffu, m1, o));
            m2 = fmaxf(m2, __shfl_xor_sync(0xffffffffu, m2, o));
        }
        if (t == 0) { red[0] = m1; red[1] = m2; }
    }
    __syncthreads();
    if (t < 128) { sc_s[t] = expf(sc_s[t] - red[0]); ps_s[t] = expf(ps_s[t] - red[1]); }
    __syncthreads();
    if (t < 32) {
        float s1 = 0.f, s2 = 0.f;
        for (int i = t; i < 128; i += 32) { s1 += sc_s[i]; s2 += ps_s[i]; }
        #pragma unroll
        for (int o = 16; o; o >>= 1) {
            s1 += __shfl_xor_sync(0xffffffffu, s1, o);
            s2 += __shfl_xor_sync(0xffffffffu, s2, o);
        }
        if (t == 0) { red[2] = 1.f / s1; red[3] = 1.f / s2; }
    }
    __syncthreads();

    // recalls -> interm
    if (t < 64) {
        float a = 0.f, pv = 0.f;
        #pragma unroll 8
        for (int n = 0; n < 128; n++) {
            float mv = mem_s[n * 65 + t];
            a  += mv * sc_s[n];
            pv += mv * ps_s[n];
        }
        g_interm[(size_t)b * CONC + IN_ + t]        = a * red[2];
        g_interm[(size_t)b * CONC + IN_ + 64 + t]   = pv * red[3];
    }
    // copy x row into interm
    {
        const float4* xs = (const float4*)(x + (size_t)b * IN_);
        float4* xd = (float4*)(g_interm + (size_t)b * CONC);
        for (int i = t; i < IN_ / 4; i += 256) xd[i] = xs[i];
    }

    // memory update: new_mem = mem*forget + gate * (rx + mem @ Wr_bot)
    // 4x4 micro-tiles over (n, m): 512 tiles, 2 per thread
    for (int tile = t; tile < 512; tile += 256) {
        int n0 = (tile >> 4) * 4;
        int m0 = (tile & 15) * 4;
        float acc[4][4] = {};
        const float* mp = mem_s + n0 * 65;
        #pragma unroll 8
        for (int k = 0; k < 64; k++) {
            float a0 = mp[k], a1 = mp[65 + k], a2 = mp[130 + k], a3 = mp[195 + k];
            const float* wp = wrb_s + k * 65 + m0;
            float b0 = wp[0], b1 = wp[1], b2 = wp[2], b3 = wp[3];
            acc[0][0] += a0 * b0; acc[0][1] += a0 * b1; acc[0][2] += a0 * b2; acc[0][3] += a0 * b3;
            acc[1][0] += a1 * b0; acc[1][1] += a1 * b1; acc[1][2] += a1 * b2; acc[1][3] += a1 * b3;
            acc[2][0] += a2 * b0; acc[2][1] += a2 * b1; acc[2][2] += a2 * b2; acc[2][3] += a2 * b3;
            acc[3][0] += a3 * b0; acc[3][1] += a3 * b1; acc[3][2] += a3 * b2; acc[3][3] += a3 * b3;
        }
        #pragma unroll
        for (int i = 0; i < 4; i++) {
            int n = n0 + i;
            float fg = f_s[n], gg = g_s[n];
            const float* mr = mem_s + n * 65;
            float4 o;
            o.x = mr[m0 + 0] * fg + gg * (rx_s[m0 + 0] + acc[i][0]);
            o.y = mr[m0 + 1] * fg + gg * (rx_s[m0 + 1] + acc[i][1]);
            o.z = mr[m0 + 2] * fg + gg * (rx_s[m0 + 2] + acc[i][2]);
            o.w = mr[m0 + 3] * fg + gg * (rx_s[m0 + 3] + acc[i][3]);
            *(float4*)&new_mem[(size_t)b * (NSLOT * MEMD) + n * MEMD + m0] = o;
        }
    }
}

// ============================================================================
// Kernel 3: output GEMM  out = interm[512,2176] @ W_o[2176,2048] + b_o
// BM=128, BN=64, BK=16, 256 threads, grid (4,32)=128 blocks
// double-buffered smem, f32x2 packed FMA (full-rate fp32)
// ============================================================================
__global__ __launch_bounds__(256) void gemm_out_kernel(
    const float* __restrict__ Bw, const float* __restrict__ bias, float* __restrict__ C)
{
    __shared__ float As[2][16][132];
    __shared__ float Bs[2][16][68];

    int t  = threadIdx.x;
    int tx = t & 15, ty = t >> 4;
    int bm0 = blockIdx.x * 128;
    int bn0 = blockIdx.y * 64;

    int la_row = t >> 2;     // 0..63 (and +64)
    int la_kq  = t & 3;
    int lb_kr  = t >> 4;     // 0..15
    int lb_cq  = t & 15;

    const int KTILES = CONC / 16;  // 136

    u64t acc[8][2];
    #pragma unroll
    for (int i = 0; i < 8; i++) { acc[i][0] = 0ull; acc[i][1] = 0ull; }

    // prologue: load ktile 0 into stage 0
    {
        float4 a0 = *(const float4*)&g_interm[(size_t)(bm0 + la_row) * CONC + la_kq * 4];
        float4 a1 = *(const float4*)&g_interm[(size_t)(bm0 + la_row + 64) * CONC + la_kq * 4];
        float4 b0 = *(const float4*)&Bw[(size_t)lb_kr * OUT_ + bn0 + lb_cq * 4];
        As[0][la_kq * 4 + 0][la_row] = a0.x; As[0][la_kq * 4 + 1][la_row] = a0.y;
        As[0][la_kq * 4 + 2][la_row] = a0.z; As[0][la_kq * 4 + 3][la_row] = a0.w;
        As[0][la_kq * 4 + 0][la_row + 64] = a1.x; As[0][la_kq * 4 + 1][la_row + 64] = a1.y;
        As[0][la_kq * 4 + 2][la_row + 64] = a1.z; As[0][la_kq * 4 + 3][la_row + 64] = a1.w;
        *(float4*)&Bs[0][lb_kr][lb_cq * 4] = b0;
    }
    __syncthreads();

    int s = 0;
    for (int kt = 0; kt < KTILES; kt++) {
        float4 na0, na1, nb0;
        bool has_next = (kt + 1 < KTILES);
        if (has_next) {
            int k0 = (kt + 1) * 16;
            na0 = *(const float4*)&g_interm[(size_t)(bm0 + la_row) * CONC + k0 + la_kq * 4];
            na1 = *(const float4*)&g_interm[(size_t)(bm0 + la_row + 64) * CONC + k0 + la_kq * 4];
            nb0 = *(const float4*)&Bw[(size_t)(k0 + lb_kr) * OUT_ + bn0 + lb_cq * 4];
        }
        #pragma unroll
        for (int k = 0; k < 16; k++) {
            float4 av0 = *(const float4*)&As[s][k][ty * 8];
            float4 av1 = *(const float4*)&As[s][k][ty * 8 + 4];
            float4 bv  = *(const float4*)&Bs[s][k][tx * 4];
            u64t bp0 = pk2(bv.x, bv.y);
            u64t bp1 = pk2(bv.z, bv.w);
            float a[8] = {av0.x, av0.y, av0.z, av0.w, av1.x, av1.y, av1.z, av1.w};
            #pragma unroll
            for (int i = 0; i < 8; i++) {
                u64t ad = pk2(a[i], a[i]);
                fma2(acc[i][0], ad, bp0);
                fma2(acc[i][1], ad, bp1);
            }
        }
        if (has_next) {
            int so = s ^ 1;
            As[so][la_kq * 4 + 0][la_row] = na0.x; As[so][la_kq * 4 + 1][la_row] = na0.y;
            As[so][la_kq * 4 + 2][la_row] = na0.z; As[so][la_kq * 4 + 3][la_row] = na0.w;
            As[so][la_kq * 4 + 0][la_row + 64] = na1.x; As[so][la_kq * 4 + 1][la_row + 64] = na1.y;
            As[so][la_kq * 4 + 2][la_row + 64] = na1.z; As[so][la_kq * 4 + 3][la_row + 64] = na1.w;
            *(float4*)&Bs[so][lb_kr][lb_cq * 4] = nb0;
            __syncthreads();
            s = so;
        }
    }

    // epilogue: add bias, store float4 per row
    int c0 = bn0 + tx * 4;
    float4 bb = make_float4(bias[c0], bias[c0 + 1], bias[c0 + 2], bias[c0 + 3]);
    #pragma unroll
    for (int i = 0; i < 8; i++) {
        int r = bm0 + ty * 8 + i;
        float2 v0 = upk2(acc[i][0]);
        float2 v1 = upk2(acc[i][1]);
        float4 o = make_float4(v0.x + bb.x, v0.y + bb.y, v1.x + bb.z, v1.y + bb.w);
        *(float4*)&C[(size_t)r * OUT_ + c0] = o;
    }
}

// ============================================================================
extern "C" void kernel_launch(void* const* d_in, const int* in_sizes, int n_in,
                              void* d_out, int out_size)
{
    const float* x      = (const float*)d_in[0];
    const float* memory = (const float*)d_in[1];
    const float* W_ar   = (const float*)d_in[2];
    const float* b_ar   = (const float*)d_in[3];
    const float* W_pr   = (const float*)d_in[4];
    const float* b_pr   = (const float*)d_in[5];
    const float* W_f    = (const float*)d_in[6];
    const float* b_f    = (const float*)d_in[7];
    const float* W_r    = (const float*)d_in[8];
    const float* b_r    = (const float*)d_in[9];
    const float* W_o    = (const float*)d_in[10];
    const float* b_o    = (const float*)d_in[11];

    float* out     = (float*)d_out;
    float* new_mem = out + (size_t)B_ * OUT_;

    cudaFuncSetAttribute(fused_mem_kernel,
                         cudaFuncAttributeMaxDynamicSharedMemorySize, FUSED_SMEM_BYTES);

    // 0: pack weights + bias-init T
    {
        int total = IN_ * NC + B_ * NC;
        pack_init_kernel<<<(total + 255) / 256, 256>>>(W_ar, b_ar, W_f, b_f, W_r, b_r);
    }
    // 1: front GEMM (split-K atomic into T)
    {
        dim3 g(8, 3, 8);
        gemm1_kernel<<<g, 256>>>(x);
    }
    // 2: fused attention + recalls + memory update (writes interm and new_mem)
    fused_mem_kernel<<<B_, 256, FUSED_SMEM_BYTES>>>(x, memory, W_pr, b_pr, W_f, W_r, new_mem);
    // 3: output GEMM
    {
        dim3 g(B_ / 128, OUT_ / 64);
        gemm_out_kernel<<<g, 256>>>(W_o, b_o, out);
    }
}